// round 9
// baseline (speedup 1.0000x reference)
#include <cuda_runtime.h>
#include <cuda_fp16.h>

#define NN 100000
#define EE 1600000
#define DD 64
#define SCAN_T 1024
#define SCAN_B ((NN + SCAN_T - 1) / SCAN_T)   // 98
#define EDGE_BLOCKS (EE / 256)                // 6250 (exact)
#define SN_BLOCKS ((NN + 255) / 256)          // 391

// ---------------- scratch (static device globals; zero-init at load) --------
// Invariant: g_deg, g_scanstate, g_smaxkey are ZERO at kernel_launch entry.
// True at load (zero-init) and restored by k_scatter each run (graph replays
// the full sequence, so the invariant holds across replays).
__device__ unsigned g_smaxkey;
__device__ float    g_smaxf;
__device__ float    g_snode[NN];
__device__ float    g_has[NN];
__device__ int      g_deg[NN];
__device__ int      g_off[NN + 1];
__device__ int      g_cur[NN];
__device__ int2     g_rc[EE];                // interleaved (row, col)
__device__ int2     g_edge[EE];              // .x = srcRow, .y = bits(exp(s-gmax))
__device__ __half2  g_xh[(size_t)NN * 32];   // fp16 mirror of x for gathers
__device__ float    g_agg[(size_t)NN * DD];
__device__ unsigned long long g_scanstate[SCAN_B];  // (flag<<32)|value

// ---------------- packed f32x2 FMA (2x fp32 FMA rate on sm_103a) ------------
union F2U { float2 f2; unsigned long long u; };
__device__ __forceinline__ F2U ffma2(F2U a, F2U b, F2U c) {
    F2U d;
    asm("fma.rn.f32x2 %0, %1, %2, %3;" : "=l"(d.u) : "l"(a.u), "l"(b.u), "l"(c.u));
    return d;
}

// ---------------- K1: FUSED (edge convert + hist) || (scores + fp16 copy) ---
__global__ void __launch_bounds__(256) k_fused(
    const float* __restrict__ x, const void* __restrict__ ei,
    const float* __restrict__ Wm, const float* __restrict__ bm) {
    int b = blockIdx.x;
    int t = threadIdx.x;
    if (b < EDGE_BLOCKS) {
        // int64 detection: probe leading 256 int64-candidates (L2 broadcast).
        // int64 non-negative ids => odd 32-bit words all zero; genuine int32
        // data there is 256 random node ids — never all zero.
        int2 probe = __ldg(&((const int2*)ei)[t]);
        int any = __syncthreads_or(probe.y);
        int e = b * 256 + t;
        int row, col;
        if (any == 0) {  // int64
            row = (int)__ldg(&((const long long*)ei)[e]);
            col = (int)__ldg(&((const long long*)ei)[(long long)EE + e]);
        } else {         // int32
            row = __ldg(&((const int*)ei)[e]);
            col = __ldg(&((const int*)ei)[EE + e]);
        }
        g_rc[e] = make_int2(row, col);
        atomicAdd(&g_deg[col], 1);
    } else {
        // ---- per-node score s = x[n].wbar + bmean ----
        __shared__ float swb[DD];
        __shared__ float sbm;
        if (t < DD) {
            float s = 0.f;
#pragma unroll
            for (int j = 0; j < DD; j++) s += __ldg(&Wm[t * DD + j]);
            swb[t] = s * (1.0f / DD);
        }
        if (t == 0) {
            float bs = 0.f;
            for (int j = 0; j < DD; j++) bs += __ldg(&bm[j]);
            sbm = bs * (1.0f / DD);
        }
        __syncthreads();
        int n0 = (b - EDGE_BLOCKS) * 256;
        int n = n0 + t;
        float s = -1e30f;
        if (n < NN) {
            const float4* xp = (const float4*)(x + (size_t)n * DD);
            float acc = 0.f;
#pragma unroll
            for (int i = 0; i < DD / 4; i++) {
                float4 v = __ldg(&xp[i]);
                acc += v.x * swb[4 * i] + v.y * swb[4 * i + 1] +
                       v.z * swb[4 * i + 2] + v.w * swb[4 * i + 3];
            }
            s = acc + sbm;  // BETA = 1.0
            g_snode[n] = s;
        }
        float m = s;
#pragma unroll
        for (int o = 16; o; o >>= 1) m = fmaxf(m, __shfl_xor_sync(0xffffffffu, m, o));
        if ((t & 31) == 0) {
            unsigned bb = __float_as_uint(m);
            unsigned key = (bb & 0x80000000u) ? ~bb : (bb | 0x80000000u);
            atomicMax(&g_smaxkey, key);
        }
        // ---- fp16 mirror, coalesced (warp handles one node's 32 half2) ----
        int lim = (NN - n0 < 256) ? (NN - n0) : 256;
        for (int j = t; j < lim * 32; j += 256) {
            int node = n0 + (j >> 5);
            int h = j & 31;
            float2 v = __ldg((const float2*)(x + (size_t)node * DD + 2 * h));
            g_xh[(size_t)node * 32 + h] = __floats2half2_rn(v.x, v.y);
        }
    }
}

// ---------------- K2: decoupled-lookback exclusive scan ---------------------
__global__ void __launch_bounds__(SCAN_T) k_scan() {
    int b = blockIdx.x, t = threadIdx.x;
    int i = b * SCAN_T + t;
    int v = (i < NN) ? g_deg[i] : 0;

    int lane = t & 31, wid = t >> 5;
    int inc = v;
#pragma unroll
    for (int o = 1; o < 32; o <<= 1) {
        int u = __shfl_up_sync(0xffffffffu, inc, o);
        if (lane >= o) inc += u;
    }
    __shared__ int wtot[32];
    __shared__ int stotal;
    __shared__ int sprefix;
    if (lane == 31) wtot[wid] = inc;
    __syncthreads();
    if (wid == 0) {
        int s = wtot[lane];
        int sinc = s;
#pragma unroll
        for (int o = 1; o < 32; o <<= 1) {
            int u = __shfl_up_sync(0xffffffffu, sinc, o);
            if (lane >= o) sinc += u;
        }
        wtot[lane] = sinc - s;
        if (lane == 31) stotal = sinc;
    }
    __syncthreads();
    int ex = wtot[wid] + inc - v;
    int total = stotal;

    if (t == 0) {
        if (b == 0) {
            atomicExch(&g_scanstate[0], (2ull << 32) | (unsigned)total);
            sprefix = 0;
            unsigned k = g_smaxkey;
            unsigned bb = (k & 0x80000000u) ? (k ^ 0x80000000u) : ~k;
            g_smaxf = __uint_as_float(bb);
        } else {
            atomicExch(&g_scanstate[b], (1ull << 32) | (unsigned)total);
            int prefix = 0;
            for (int j = b - 1; j >= 0;) {
                unsigned long long st;
                do { st = atomicAdd(&g_scanstate[j], 0ull); } while ((st >> 32) == 0ull);
                prefix += (int)(unsigned)st;
                if ((st >> 32) == 2ull) break;
                j--;
            }
            atomicExch(&g_scanstate[b], (2ull << 32) | (unsigned)(prefix + total));
            sprefix = prefix;
        }
    }
    __syncthreads();
    int off = sprefix + ex;
    if (i < NN) { g_off[i] = off; g_cur[i] = off; }
    if (b == SCAN_B - 1 && t == 0) g_off[NN] = sprefix + total;  // == EE
}

// ---------------- K3: scatter (row, w) into CSR-by-dest + cleanup -----------
__global__ void __launch_bounds__(256) k_scatter() {
    int e = blockIdx.x * 256 + threadIdx.x;  // grid covers EE exactly
    int2 rc = __ldg(&g_rc[e]);
    float w = __expf(__ldg(&g_snode[rc.x]) - g_smaxf);
    int pos = atomicAdd(&g_cur[rc.y], 1);
    g_edge[pos] = make_int2(rc.x, __float_as_int(w));
    // restore zero-invariants for the next graph replay
    if (e < NN) g_deg[e] = 0;
    if (e < SCAN_B) g_scanstate[e] = 0ull;
    if (e == 0) g_smaxkey = 0u;
}

// ---------------- K4: warp-per-node aggregation (fp16 gather, no shuffles) --
// lane owns dims {2*lane, 2*lane+1}; sumw computed identically by all lanes.
__global__ void __launch_bounds__(256) k_agg() {
    int n = (blockIdx.x * blockDim.x + threadIdx.x) >> 5;
    int lane = threadIdx.x & 31;
    if (n >= NN) return;
    int beg = g_off[n], end = g_off[n + 1];

    float2 acc = make_float2(0.f, 0.f);
    float sumw = 0.f;
#pragma unroll 4
    for (int i = beg; i < end; i++) {
        int2 ed = __ldg(&g_edge[i]);              // broadcast within warp
        float w = __int_as_float(ed.y);
        sumw += w;
        float2 v = __half22float2(g_xh[(size_t)ed.x * 32 + lane]);
        acc.x += w * v.x;
        acc.y += w * v.y;
    }
    float inv = (sumw > 0.f) ? (1.0f / sumw) : 0.f;
    ((float2*)(g_agg + (size_t)n * DD))[lane] = make_float2(acc.x * inv, acc.y * inv);
    if (lane == 0) g_has[n] = (sumw > 0.f) ? 1.0f : 0.0f;
}

// ---------------- K5: out = agg@Wm + has*bm + x@Wr + br ---------------------
// 256 nodes x 64 cols per block; thread = 8 nodes x 8 cols, f32x2 FMAs.
#define SA_STRIDE 260
__global__ void __launch_bounds__(256, 1) k_out(
    const float* __restrict__ x,
    const float* __restrict__ Wm, const float* __restrict__ bm,
    const float* __restrict__ Wr, const float* __restrict__ br,
    float* __restrict__ out) {
    __shared__ float sAk[32 * SA_STRIDE];  // [k within chunk][node]
    __shared__ float sWs[32 * 64];         // [k within chunk][col]

    int t = threadIdx.x;
    int cg = t & 7;
    int ng = t >> 3;
    int nb0 = blockIdx.x * 256;

    float4 bm0 = __ldg((const float4*)(bm + cg * 8));
    float4 bm1 = __ldg((const float4*)(bm + cg * 8 + 4));
    float4 br0 = __ldg((const float4*)(br + cg * 8));
    float4 br1 = __ldg((const float4*)(br + cg * 8 + 4));

    F2U acc[8][4];
#pragma unroll
    for (int i = 0; i < 8; i++)
#pragma unroll
        for (int p = 0; p < 4; p++) acc[i][p].u = 0ull;

    int node = nb0 + t;
    for (int kc = 0; kc < 4; kc++) {
        const float* Asrc = (kc < 2) ? g_agg : x;
        int koff = (kc < 2) ? kc * 32 : (kc - 2) * 32;
        const float* Wsrc = (kc < 2) ? (Wm + kc * 32 * 64) : (Wr + (kc - 2) * 32 * 64);
        __syncthreads();
        const float4* ap = (const float4*)(Asrc + (size_t)node * DD + koff);
#pragma unroll
        for (int kq = 0; kq < 8; kq++) {
            float4 v = (node < NN) ? __ldg(&ap[kq]) : make_float4(0.f, 0.f, 0.f, 0.f);
            sAk[(kq * 4 + 0) * SA_STRIDE + t] = v.x;
            sAk[(kq * 4 + 1) * SA_STRIDE + t] = v.y;
            sAk[(kq * 4 + 2) * SA_STRIDE + t] = v.z;
            sAk[(kq * 4 + 3) * SA_STRIDE + t] = v.w;
        }
        ((float4*)sWs)[t] = __ldg(&((const float4*)Wsrc)[t]);
        ((float4*)sWs)[t + 256] = __ldg(&((const float4*)Wsrc)[t + 256]);
        __syncthreads();

#pragma unroll 4
        for (int kk = 0; kk < 32; kk++) {
            float4 wa = *(const float4*)&sWs[kk * 64 + cg * 8];
            float4 wb = *(const float4*)&sWs[kk * 64 + cg * 8 + 4];
            F2U w0, w1, w2, w3;
            w0.f2 = make_float2(wa.x, wa.y); w1.f2 = make_float2(wa.z, wa.w);
            w2.f2 = make_float2(wb.x, wb.y); w3.f2 = make_float2(wb.z, wb.w);
            float4 a03 = *(const float4*)&sAk[kk * SA_STRIDE + ng * 8];
            float4 a47 = *(const float4*)&sAk[kk * SA_STRIDE + ng * 8 + 4];
            float av[8] = {a03.x, a03.y, a03.z, a03.w, a47.x, a47.y, a47.z, a47.w};
#pragma unroll
            for (int i = 0; i < 8; i++) {
                F2U ap2; ap2.f2 = make_float2(av[i], av[i]);
                acc[i][0] = ffma2(ap2, w0, acc[i][0]);
                acc[i][1] = ffma2(ap2, w1, acc[i][1]);
                acc[i][2] = ffma2(ap2, w2, acc[i][2]);
                acc[i][3] = ffma2(ap2, w3, acc[i][3]);
            }
        }
    }

#pragma unroll
    for (int i = 0; i < 8; i++) {
        int n = nb0 + ng * 8 + i;
        if (n >= NN) break;
        float h = g_has[n];
        float4 o0 = make_float4(acc[i][0].f2.x + h * bm0.x + br0.x,
                                acc[i][0].f2.y + h * bm0.y + br0.y,
                                acc[i][1].f2.x + h * bm0.z + br0.z,
                                acc[i][1].f2.y + h * bm0.w + br0.w);
        float4 o1 = make_float4(acc[i][2].f2.x + h * bm1.x + br1.x,
                                acc[i][2].f2.y + h * bm1.y + br1.y,
                                acc[i][3].f2.x + h * bm1.z + br1.z,
                                acc[i][3].f2.y + h * bm1.w + br1.w);
        float* op = out + (size_t)n * DD + cg * 8;
        *(float4*)op = o0;
        *(float4*)(op + 4) = o1;
    }
}

// ---------------- launcher ---------------------------------------------------
extern "C" void kernel_launch(void* const* d_in, const int* in_sizes, int n_in,
                              void* d_out, int out_size) {
    const float* x  = (const float*)d_in[0];
    const void*  ei = d_in[1];
    const float* Wm = (const float*)d_in[2];
    const float* bm = (const float*)d_in[3];
    const float* Wr = (const float*)d_in[4];
    const float* br = (const float*)d_in[5];
    float* out = (float*)d_out;

    k_fused<<<EDGE_BLOCKS + SN_BLOCKS, 256>>>(x, ei, Wm, bm);
    k_scan<<<SCAN_B, SCAN_T>>>();
    k_scatter<<<EDGE_BLOCKS, 256>>>();
    k_agg<<<(NN + 7) / 8, 256>>>();
    k_out<<<SN_BLOCKS, 256>>>(x, Wm, bm, Wr, br, out);
}

// round 10
// speedup vs baseline: 1.0475x; 1.0475x over previous
#include <cuda_runtime.h>
#include <cuda_fp16.h>

#define NN 100000
#define EE 1600000
#define DD 64
#define SCAN_T 1024
#define SCAN_B ((NN + SCAN_T - 1) / SCAN_T)   // 98
#define EDGE_BLOCKS (EE / 256)                // 6250 (exact)
#define SN_BLOCKS ((NN + 255) / 256)          // 391

// ---------------- scratch (static device globals; zero-init at load) --------
// Invariant: g_deg, g_scanstate, g_smaxkey are ZERO at kernel_launch entry.
// True at load (zero-init) and restored by k_scatter on every run.
__device__ unsigned g_smaxkey;
__device__ float    g_snode[NN];             // score, then exp(s-gmax) in-place
__device__ float    g_has[NN];
__device__ int      g_deg[NN];
__device__ int      g_off[NN + 1];
__device__ int      g_cur[NN];
__device__ int2     g_rc[EE];                // interleaved (row, col)
__device__ int      g_eidx[EE];              // CSR-by-dest: srcRow only
__device__ __half2  g_xh[(size_t)NN * 32];   // fp16 mirror of x for gathers
__device__ float    g_agg[(size_t)NN * DD];
__device__ unsigned long long g_scanstate[SCAN_B];  // (flag<<32)|value

// ---------------- packed f32x2 FMA (2x fp32 FMA rate on sm_103a) ------------
union F2U { float2 f2; unsigned long long u; };
__device__ __forceinline__ F2U ffma2(F2U a, F2U b, F2U c) {
    F2U d;
    asm("fma.rn.f32x2 %0, %1, %2, %3;" : "=l"(d.u) : "l"(a.u), "l"(b.u), "l"(c.u));
    return d;
}

// ---------------- K1: FUSED (edge convert + hist) || (scores + fp16 copy) ---
__global__ void __launch_bounds__(256) k_fused(
    const float* __restrict__ x, const void* __restrict__ ei,
    const float* __restrict__ Wm, const float* __restrict__ bm) {
    int b = blockIdx.x;
    int t = threadIdx.x;
    if (b < EDGE_BLOCKS) {
        // int64 detection: leading odd 32-bit words all zero <=> int64 ids.
        int2 probe = __ldg(&((const int2*)ei)[t]);
        int any = __syncthreads_or(probe.y);
        int e = b * 256 + t;
        int row, col;
        if (any == 0) {  // int64
            row = (int)__ldg(&((const long long*)ei)[e]);
            col = (int)__ldg(&((const long long*)ei)[(long long)EE + e]);
        } else {         // int32
            row = __ldg(&((const int*)ei)[e]);
            col = __ldg(&((const int*)ei)[EE + e]);
        }
        g_rc[e] = make_int2(row, col);
        atomicAdd(&g_deg[col], 1);
    } else {
        // ---- per-node score s = x[n].wbar + bmean ----
        __shared__ float swb[DD];
        __shared__ float sbm;
        if (t < DD) {
            float s = 0.f;
#pragma unroll
            for (int j = 0; j < DD; j++) s += __ldg(&Wm[t * DD + j]);
            swb[t] = s * (1.0f / DD);
        }
        if (t == 0) {
            float bs = 0.f;
            for (int j = 0; j < DD; j++) bs += __ldg(&bm[j]);
            sbm = bs * (1.0f / DD);
        }
        __syncthreads();
        int n0 = (b - EDGE_BLOCKS) * 256;
        int n = n0 + t;
        float s = -1e30f;
        if (n < NN) {
            const float4* xp = (const float4*)(x + (size_t)n * DD);
            float acc = 0.f;
#pragma unroll
            for (int i = 0; i < DD / 4; i++) {
                float4 v = __ldg(&xp[i]);
                acc += v.x * swb[4 * i] + v.y * swb[4 * i + 1] +
                       v.z * swb[4 * i + 2] + v.w * swb[4 * i + 3];
            }
            s = acc + sbm;  // BETA = 1.0
            g_snode[n] = s;
        }
        float m = s;
#pragma unroll
        for (int o = 16; o; o >>= 1) m = fmaxf(m, __shfl_xor_sync(0xffffffffu, m, o));
        if ((t & 31) == 0) {
            unsigned bb = __float_as_uint(m);
            unsigned key = (bb & 0x80000000u) ? ~bb : (bb | 0x80000000u);
            atomicMax(&g_smaxkey, key);
        }
        // ---- fp16 mirror, coalesced ----
        int lim = (NN - n0 < 256) ? (NN - n0) : 256;
        for (int j = t; j < lim * 32; j += 256) {
            int node = n0 + (j >> 5);
            int h = j & 31;
            float2 v = __ldg((const float2*)(x + (size_t)node * DD + 2 * h));
            g_xh[(size_t)node * 32 + h] = __floats2half2_rn(v.x, v.y);
        }
    }
}

// ---------------- K2: decoupled-lookback scan + snode -> exp(s-gmax) --------
__global__ void __launch_bounds__(SCAN_T) k_scan() {
    int b = blockIdx.x, t = threadIdx.x;
    int i = b * SCAN_T + t;
    int v = (i < NN) ? g_deg[i] : 0;

    // in-place weight conversion (smaxkey is final after k_fused)
    if (i < NN) {
        unsigned k = g_smaxkey;
        unsigned bb = (k & 0x80000000u) ? (k ^ 0x80000000u) : ~k;
        float smax = __uint_as_float(bb);
        g_snode[i] = __expf(g_snode[i] - smax);
    }

    int lane = t & 31, wid = t >> 5;
    int inc = v;
#pragma unroll
    for (int o = 1; o < 32; o <<= 1) {
        int u = __shfl_up_sync(0xffffffffu, inc, o);
        if (lane >= o) inc += u;
    }
    __shared__ int wtot[32];
    __shared__ int stotal;
    __shared__ int sprefix;
    if (lane == 31) wtot[wid] = inc;
    __syncthreads();
    if (wid == 0) {
        int s = wtot[lane];
        int sinc = s;
#pragma unroll
        for (int o = 1; o < 32; o <<= 1) {
            int u = __shfl_up_sync(0xffffffffu, sinc, o);
            if (lane >= o) sinc += u;
        }
        wtot[lane] = sinc - s;
        if (lane == 31) stotal = sinc;
    }
    __syncthreads();
    int ex = wtot[wid] + inc - v;
    int total = stotal;

    if (t == 0) {
        if (b == 0) {
            atomicExch(&g_scanstate[0], (2ull << 32) | (unsigned)total);
            sprefix = 0;
        } else {
            atomicExch(&g_scanstate[b], (1ull << 32) | (unsigned)total);
            int prefix = 0;
            for (int j = b - 1; j >= 0;) {
                unsigned long long st;
                do { st = atomicAdd(&g_scanstate[j], 0ull); } while ((st >> 32) == 0ull);
                prefix += (int)(unsigned)st;
                if ((st >> 32) == 2ull) break;
                j--;
            }
            atomicExch(&g_scanstate[b], (2ull << 32) | (unsigned)(prefix + total));
            sprefix = prefix;
        }
    }
    __syncthreads();
    int off = sprefix + ex;
    if (i < NN) { g_off[i] = off; g_cur[i] = off; }
    if (b == SCAN_B - 1 && t == 0) g_off[NN] = sprefix + total;  // == EE
}

// ---------------- K3: scatter srcRow into CSR-by-dest + cleanup -------------
__global__ void __launch_bounds__(256) k_scatter() {
    int e = blockIdx.x * 256 + threadIdx.x;  // grid covers EE exactly
    int2 rc = __ldg(&g_rc[e]);
    int pos = atomicAdd(&g_cur[rc.y], 1);
    g_eidx[pos] = rc.x;
    // restore zero-invariants for the next graph replay
    if (e < NN) g_deg[e] = 0;
    if (e < SCAN_B) g_scanstate[e] = 0ull;
    if (e == 0) g_smaxkey = 0u;
}

// ---------------- K4: warp-per-node aggregation, 4 edges/iteration ----------
// 8 lanes per edge; lane's LDG.128 covers 8 fp16 dims. w = g_snode[row]
// (already exp(s-gmax), L2-resident 400KB).
__global__ void __launch_bounds__(256) k_agg() {
    int n = (blockIdx.x * blockDim.x + threadIdx.x) >> 5;
    int lane = threadIdx.x & 31;
    if (n >= NN) return;
    int beg = g_off[n], end = g_off[n + 1];
    int grp = lane >> 3;   // edge slot 0..3
    int q = lane & 7;      // dim octet: dims 8q..8q+7

    F2U a0, a1, a2, a3;
    a0.u = a1.u = a2.u = a3.u = 0ull;
    float sumw = 0.f;
#pragma unroll 2
    for (int i = beg + grp; i < end; i += 4) {
        int row = __ldg(&g_eidx[i]);
        float w = __ldg(&g_snode[row]);
        sumw += w;
        uint4 hv = __ldg((const uint4*)(g_xh + (size_t)row * 32 + q * 4));
        F2U wp; wp.f2 = make_float2(w, w);
        F2U f0, f1, f2, f3;
        f0.f2 = __half22float2(*(__half2*)&hv.x);
        f1.f2 = __half22float2(*(__half2*)&hv.y);
        f2.f2 = __half22float2(*(__half2*)&hv.z);
        f3.f2 = __half22float2(*(__half2*)&hv.w);
        a0 = ffma2(wp, f0, a0);
        a1 = ffma2(wp, f1, a1);
        a2 = ffma2(wp, f2, a2);
        a3 = ffma2(wp, f3, a3);
    }
    // combine the 4 edge groups (lanes q, q+8, q+16, q+24 hold same dims)
#pragma unroll
    for (int o = 8; o <= 16; o <<= 1) {
        a0.f2.x += __shfl_xor_sync(0xffffffffu, a0.f2.x, o);
        a0.f2.y += __shfl_xor_sync(0xffffffffu, a0.f2.y, o);
        a1.f2.x += __shfl_xor_sync(0xffffffffu, a1.f2.x, o);
        a1.f2.y += __shfl_xor_sync(0xffffffffu, a1.f2.y, o);
        a2.f2.x += __shfl_xor_sync(0xffffffffu, a2.f2.x, o);
        a2.f2.y += __shfl_xor_sync(0xffffffffu, a2.f2.y, o);
        a3.f2.x += __shfl_xor_sync(0xffffffffu, a3.f2.x, o);
        a3.f2.y += __shfl_xor_sync(0xffffffffu, a3.f2.y, o);
        sumw += __shfl_xor_sync(0xffffffffu, sumw, o);
    }
    float inv = (sumw > 0.f) ? (1.0f / sumw) : 0.f;
    if (grp == 0) {  // lanes 0..7 write dims 8q..8q+7
        float* op = g_agg + (size_t)n * DD + q * 8;
        *(float4*)op = make_float4(a0.f2.x * inv, a0.f2.y * inv,
                                   a1.f2.x * inv, a1.f2.y * inv);
        *(float4*)(op + 4) = make_float4(a2.f2.x * inv, a2.f2.y * inv,
                                         a3.f2.x * inv, a3.f2.y * inv);
    }
    if (lane == 0) g_has[n] = (sumw > 0.f) ? 1.0f : 0.0f;
}

// ---------------- K5: out = agg@Wm + has*bm + x@Wr + br ---------------------
#define SA_STRIDE 260
__global__ void __launch_bounds__(256, 1) k_out(
    const float* __restrict__ x,
    const float* __restrict__ Wm, const float* __restrict__ bm,
    const float* __restrict__ Wr, const float* __restrict__ br,
    float* __restrict__ out) {
    __shared__ float sAk[32 * SA_STRIDE];  // [k within chunk][node]
    __shared__ float sWs[32 * 64];         // [k within chunk][col]

    int t = threadIdx.x;
    int cg = t & 7;
    int ng = t >> 3;
    int nb0 = blockIdx.x * 256;

    float4 bm0 = __ldg((const float4*)(bm + cg * 8));
    float4 bm1 = __ldg((const float4*)(bm + cg * 8 + 4));
    float4 br0 = __ldg((const float4*)(br + cg * 8));
    float4 br1 = __ldg((const float4*)(br + cg * 8 + 4));

    F2U acc[8][4];
#pragma unroll
    for (int i = 0; i < 8; i++)
#pragma unroll
        for (int p = 0; p < 4; p++) acc[i][p].u = 0ull;

    int node = nb0 + t;
    for (int kc = 0; kc < 4; kc++) {
        const float* Asrc = (kc < 2) ? g_agg : x;
        int koff = (kc < 2) ? kc * 32 : (kc - 2) * 32;
        const float* Wsrc = (kc < 2) ? (Wm + kc * 32 * 64) : (Wr + (kc - 2) * 32 * 64);
        __syncthreads();
        const float4* ap = (const float4*)(Asrc + (size_t)node * DD + koff);
#pragma unroll
        for (int kq = 0; kq < 8; kq++) {
            float4 v = (node < NN) ? __ldg(&ap[kq]) : make_float4(0.f, 0.f, 0.f, 0.f);
            sAk[(kq * 4 + 0) * SA_STRIDE + t] = v.x;
            sAk[(kq * 4 + 1) * SA_STRIDE + t] = v.y;
            sAk[(kq * 4 + 2) * SA_STRIDE + t] = v.z;
            sAk[(kq * 4 + 3) * SA_STRIDE + t] = v.w;
        }
        ((float4*)sWs)[t] = __ldg(&((const float4*)Wsrc)[t]);
        ((float4*)sWs)[t + 256] = __ldg(&((const float4*)Wsrc)[t + 256]);
        __syncthreads();

#pragma unroll 4
        for (int kk = 0; kk < 32; kk++) {
            float4 wa = *(const float4*)&sWs[kk * 64 + cg * 8];
            float4 wb = *(const float4*)&sWs[kk * 64 + cg * 8 + 4];
            F2U w0, w1, w2, w3;
            w0.f2 = make_float2(wa.x, wa.y); w1.f2 = make_float2(wa.z, wa.w);
            w2.f2 = make_float2(wb.x, wb.y); w3.f2 = make_float2(wb.z, wb.w);
            float4 a03 = *(const float4*)&sAk[kk * SA_STRIDE + ng * 8];
            float4 a47 = *(const float4*)&sAk[kk * SA_STRIDE + ng * 8 + 4];
            float av[8] = {a03.x, a03.y, a03.z, a03.w, a47.x, a47.y, a47.z, a47.w};
#pragma unroll
            for (int i = 0; i < 8; i++) {
                F2U ap2; ap2.f2 = make_float2(av[i], av[i]);
                acc[i][0] = ffma2(ap2, w0, acc[i][0]);
                acc[i][1] = ffma2(ap2, w1, acc[i][1]);
                acc[i][2] = ffma2(ap2, w2, acc[i][2]);
                acc[i][3] = ffma2(ap2, w3, acc[i][3]);
            }
        }
    }

#pragma unroll
    for (int i = 0; i < 8; i++) {
        int n = nb0 + ng * 8 + i;
        if (n >= NN) break;
        float h = g_has[n];
        float4 o0 = make_float4(acc[i][0].f2.x + h * bm0.x + br0.x,
                                acc[i][0].f2.y + h * bm0.y + br0.y,
                                acc[i][1].f2.x + h * bm0.z + br0.z,
                                acc[i][1].f2.y + h * bm0.w + br0.w);
        float4 o1 = make_float4(acc[i][2].f2.x + h * bm1.x + br1.x,
                                acc[i][2].f2.y + h * bm1.y + br1.y,
                                acc[i][3].f2.x + h * bm1.z + br1.z,
                                acc[i][3].f2.y + h * bm1.w + br1.w);
        float* op = out + (size_t)n * DD + cg * 8;
        *(float4*)op = o0;
        *(float4*)(op + 4) = o1;
    }
}

// ---------------- launcher ---------------------------------------------------
extern "C" void kernel_launch(void* const* d_in, const int* in_sizes, int n_in,
                              void* d_out, int out_size) {
    const float* x  = (const float*)d_in[0];
    const void*  ei = d_in[1];
    const float* Wm = (const float*)d_in[2];
    const float* bm = (const float*)d_in[3];
    const float* Wr = (const float*)d_in[4];
    const float* br = (const float*)d_in[5];
    float* out = (float*)d_out;

    k_fused<<<EDGE_BLOCKS + SN_BLOCKS, 256>>>(x, ei, Wm, bm);
    k_scan<<<SCAN_B, SCAN_T>>>();
    k_scatter<<<EDGE_BLOCKS, 256>>>();
    k_agg<<<(NN + 7) / 8, 256>>>();
    k_out<<<SN_BLOCKS, 256>>>(x, Wm, bm, Wr, br, out);
}